// round 1
// baseline (speedup 1.0000x reference)
#include <cuda_runtime.h>
#include <cuda_bf16.h>

// MedianFilter1D: k=9 sliding median along last axis, replicate padding.
// x: [B, C, L] fp32 with L = 8192. One CTA per row (B*C rows).
//
// Strategy:
//  - Stage the 32KB row in shared memory with a 4-element replicate halo.
//  - Each thread computes 4 consecutive outputs per iteration from 12
//    contiguous values (3x LDS.128), using the sorted-triple median identity
//    with the two middle triples shared across the 4 outputs (21 min/max
//    ops per output vs ~30 naive).
//  - float4 coalesced loads and stores throughout.

#define ROW_L 8192
#define PAD   4
#define NTHREADS 256

__device__ __forceinline__ void cswap(float& a, float& b) {
    float lo = fminf(a, b);
    b = fmaxf(a, b);
    a = lo;
}

__device__ __forceinline__ void sort3(float& a, float& b, float& c) {
    cswap(a, b);
    cswap(b, c);
    cswap(a, b);
}

__device__ __forceinline__ float med3(float a, float b, float c) {
    // median of 3: max(min(a,b), min(max(a,b), c))
    return fmaxf(fminf(a, b), fminf(fmaxf(a, b), c));
}

// median of 9 given three SORTED triples (a0<=a1<=a2, etc.)
__device__ __forceinline__ float combine9(float a0, float a1, float a2,
                                          float b0, float b1, float b2,
                                          float c0, float c1, float c2) {
    float lo  = fmaxf(fmaxf(a0, b0), c0);   // max of mins
    float mid = med3(a1, b1, c1);           // med of mids
    float hi  = fminf(fminf(a2, b2), c2);   // min of maxs
    return med3(lo, mid, hi);
}

__global__ __launch_bounds__(NTHREADS, 4)
void median9_kernel(const float* __restrict__ x, float* __restrict__ y) {
    __shared__ __align__(16) float s[ROW_L + 2 * PAD];

    const int row = blockIdx.x;
    const float* xr = x + (size_t)row * ROW_L;
    float* yr       = y + (size_t)row * ROW_L;
    const int t = threadIdx.x;

    // ---- Load row into smem (float4, coalesced). s[PAD + i] = xr[i]. ----
    const float4* x4 = (const float4*)xr;
    #pragma unroll
    for (int j = 0; j < ROW_L / 4 / NTHREADS; j++) {
        int i = t + NTHREADS * j;          // float4 index within row
        float4 v = x4[i];
        *(float4*)&s[PAD + 4 * i] = v;
    }
    if (t == 0) {
        float a = xr[0];
        float b = xr[ROW_L - 1];
        s[0] = a; s[1] = a; s[2] = a; s[3] = a;
        s[ROW_L + PAD + 0] = b;
        s[ROW_L + PAD + 1] = b;
        s[ROW_L + PAD + 2] = b;
        s[ROW_L + PAD + 3] = b;
    }
    __syncthreads();

    // ---- Compute: each iteration, 4 consecutive outputs from 12 values. ----
    // Output position p uses window s[p .. p+8].
    #pragma unroll
    for (int j = 0; j < ROW_L / 4 / NTHREADS; j++) {
        const int o = 4 * t + 4 * NTHREADS * j;   // output base (multiple of 4)

        float4 va = *(const float4*)&s[o];        // v0..v3
        float4 vb = *(const float4*)&s[o + 4];    // v4..v7
        float4 vc = *(const float4*)&s[o + 8];    // v8..v11

        const float v0 = va.x, v1 = va.y, v2 = va.z, v3 = va.w;
        const float v4 = vb.x, v5 = vb.y, v6 = vb.z, v7 = vb.w;
        const float v8 = vc.x, v9 = vc.y, v10 = vc.z, v11 = vc.w;

        // Shared middle triples for all four windows
        float b0 = v3, b1 = v4, b2 = v5; sort3(b0, b1, b2);
        float c0 = v6, c1 = v7, c2 = v8; sort3(c0, c1, c2);

        float4 r;

        // out p=o:   window {v0..v8}  = {v0,v1,v2} u T1 u T2
        { float a0 = v0, a1 = v1, a2 = v2; sort3(a0, a1, a2);
          r.x = combine9(a0, a1, a2, b0, b1, b2, c0, c1, c2); }

        // out p=o+1: window {v1..v9}  = {v1,v2,v9} u T1 u T2
        { float a0 = v1, a1 = v2, a2 = v9; sort3(a0, a1, a2);
          r.y = combine9(a0, a1, a2, b0, b1, b2, c0, c1, c2); }

        // out p=o+2: window {v2..v10} = {v2,v9,v10} u T1 u T2
        { float a0 = v2, a1 = v9, a2 = v10; sort3(a0, a1, a2);
          r.z = combine9(a0, a1, a2, b0, b1, b2, c0, c1, c2); }

        // out p=o+3: window {v3..v11} = {v9,v10,v11} u T1 u T2
        { float a0 = v9, a1 = v10, a2 = v11; sort3(a0, a1, a2);
          r.w = combine9(a0, a1, a2, b0, b1, b2, c0, c1, c2); }

        *(float4*)(yr + o) = r;
    }
}

extern "C" void kernel_launch(void* const* d_in, const int* in_sizes, int n_in,
                              void* d_out, int out_size) {
    const float* x = (const float*)d_in[0];
    float* y = (float*)d_out;
    // kernel_size (d_in[1]) is statically 9 for this problem.
    const int rows = in_sizes[0] / ROW_L;   // B*C = 2048
    median9_kernel<<<rows, NTHREADS>>>(x, y);
}

// round 2
// speedup vs baseline: 1.1071x; 1.1071x over previous
#include <cuda_runtime.h>
#include <cuda_bf16.h>

// MedianFilter1D: k=9 sliding median along last axis, replicate padding.
// x: [B, C, L] fp32, L = 8192. One CTA per row (B*C = 2048 rows).
//
// R2 changes vs R1 (29.8us, alu=57.5% dram=39.5% occ=43%):
//  - 17 min/max ops per output (was 21): hoist shared-triple reductions
//    (mm, nn, clamp bounds p/q) and reuse sorted pairs for the a-triples.
//  - __launch_bounds__(256,5): regs 64 -> <=51, occupancy 50% -> 62.5%.
//  - halo filled from registers (no serial scalar LDGs before the barrier).

#define ROW_L 8192
#define PAD   4
#define NTHREADS 256
#define ITERS (ROW_L / 4 / NTHREADS)   // 8

__device__ __forceinline__ void cswap(float& a, float& b) {
    float lo = fminf(a, b);
    b = fmaxf(a, b);
    a = lo;
}

__device__ __forceinline__ void sort3(float& a, float& b, float& c) {
    cswap(a, b);
    cswap(b, c);
    cswap(a, b);
}

__device__ __forceinline__ float med3(float a, float b, float c) {
    return fmaxf(fminf(a, b), fminf(fmaxf(a, b), c));   // 4 ops
}

// Insert x into sorted pair (p0 <= p1): a0 <= a1 <= a2 (4 ops)
__device__ __forceinline__ void insert3(float x, float p0, float p1,
                                        float& a0, float& a1, float& a2) {
    a0 = fminf(x, p0);
    float m = fmaxf(x, p0);
    a1 = fminf(m, p1);
    a2 = fmaxf(m, p1);
}

__global__ __launch_bounds__(NTHREADS, 5)
void median9_kernel(const float* __restrict__ x, float* __restrict__ y) {
    __shared__ __align__(16) float s[ROW_L + 2 * PAD];

    const int row = blockIdx.x;
    const float* xr = x + (size_t)row * ROW_L;
    float* yr       = y + (size_t)row * ROW_L;
    const int t = threadIdx.x;

    // ---- Stage row into smem (float4, coalesced). s[PAD + i] = xr[i]. ----
    const float4* x4 = (const float4*)xr;
    #pragma unroll
    for (int j = 0; j < ITERS; j++) {
        int i = t + NTHREADS * j;
        float4 v = x4[i];
        *(float4*)&s[PAD + 4 * i] = v;
        if (j == 0 && t == 0) {            // left replicate halo from v.x
            s[0] = v.x; s[1] = v.x; s[2] = v.x; s[3] = v.x;
        }
        if (j == ITERS - 1 && t == NTHREADS - 1) {  // right halo from v.w
            s[ROW_L + PAD + 0] = v.w;
            s[ROW_L + PAD + 1] = v.w;
            s[ROW_L + PAD + 2] = v.w;
            s[ROW_L + PAD + 3] = v.w;
        }
    }
    __syncthreads();

    // ---- 4 consecutive outputs per iteration from 12 values. ----
    // Output p uses window s[p .. p+8] (p indexes the padded array).
    #pragma unroll
    for (int j = 0; j < ITERS; j++) {
        const int o = 4 * t + 4 * NTHREADS * j;    // output base (mult of 4)

        float4 va = *(const float4*)&s[o];         // v0..v3
        float4 vb = *(const float4*)&s[o + 4];     // v4..v7
        float4 vc = *(const float4*)&s[o + 8];     // v8..v11

        // Shared middle triples T1={v3,v4,v5}, T2={v6,v7,v8}, sorted.
        float b0 = va.w, b1 = vb.x, b2 = vb.y; sort3(b0, b1, b2);  // 6
        float c0 = vb.z, c1 = vb.w, c2 = vc.x; sort3(c0, c1, c2);  // 6

        // Hoisted reductions over the shared triples.
        const float mm = fmaxf(b0, c0);            // 1  (max of T-mins)
        const float nn = fminf(b2, c2);            // 1  (min of T-maxes)
        const float p  = fminf(b1, c1);            // 1  clamp lo
        const float q  = fmaxf(b1, c1);            // 1  clamp hi

        // Sorted pairs reused by the a-triples.
        float s1 = fminf(va.y, va.z), s2 = fmaxf(va.y, va.z);  // (v1,v2)  2
        float t1 = fminf(vc.y, vc.z), t2 = fmaxf(vc.y, vc.z);  // (v9,v10) 2

        float4 r;
        float a0, a1, a2;

        // out o:   {v0,v1,v2} u T1 u T2
        insert3(va.x, s1, s2, a0, a1, a2);                       // 4
        r.x = med3(fmaxf(a0, mm), fmaxf(p, fminf(q, a1)), fminf(a2, nn)); // 8

        // out o+1: {v1,v2,v9} u T1 u T2
        insert3(vc.y, s1, s2, a0, a1, a2);
        r.y = med3(fmaxf(a0, mm), fmaxf(p, fminf(q, a1)), fminf(a2, nn));

        // out o+2: {v2,v9,v10} u T1 u T2
        insert3(va.z, t1, t2, a0, a1, a2);
        r.z = med3(fmaxf(a0, mm), fmaxf(p, fminf(q, a1)), fminf(a2, nn));

        // out o+3: {v9,v10,v11} u T1 u T2
        insert3(vc.w, t1, t2, a0, a1, a2);
        r.w = med3(fmaxf(a0, mm), fmaxf(p, fminf(q, a1)), fminf(a2, nn));

        *(float4*)(yr + o) = r;
    }
}

extern "C" void kernel_launch(void* const* d_in, const int* in_sizes, int n_in,
                              void* d_out, int out_size) {
    const float* x = (const float*)d_in[0];
    float* y = (float*)d_out;
    const int rows = in_sizes[0] / ROW_L;   // B*C = 2048
    median9_kernel<<<rows, NTHREADS>>>(x, y);
}